// round 16
// baseline (speedup 1.0000x reference)
#include <cuda_runtime.h>
#include <math.h>

#define BB 64
#define NN 16800
#define CC 21
#define SS 66            // 256-anchor units per batch
#define NW 8             // warps per K1 block
#define NPART (SS * NW)  // 528 per-warp partials per batch
#define NV4 4200         // NN / 4
#define TINY_CAP 2560
#define FP32_EPS 1.1920928955078125e-07f

// scratch (no cudaMalloc allowed)
__device__ unsigned int g_bits[BB * NN];      // labels_neg fp32 bits (all >= +0)
__device__ float g_part_lb[BB * NPART];
__device__ float g_part_cp[BB * NPART];
__device__ int   g_part_pn[BB * NPART];
__device__ float g_batch[BB * 3];

__device__ __forceinline__ float sl1f(float d) {
    float a = fabsf(d);
    return a < 1.0f ? 0.5f * d * d : a - 0.5f;
}

// ---------------------------------------------------------------------------
// K1: one block = one 256-anchor unit. Per-warp shfl reduction only.
// ---------------------------------------------------------------------------
__global__ __launch_bounds__(256) void k1_main(
    const float* __restrict__ p_bboxs,
    const float* __restrict__ g_bboxs,
    const float* __restrict__ p_labels,
    const int*   __restrict__ g_labels,
    const float* __restrict__ ancs)
{
    __shared__ float sh[8][672];          // 8 warps x 32 anchors x 21 floats

    const int b   = blockIdx.y;
    const int tid = threadIdx.x;
    const int w   = tid >> 5;
    const int l   = tid & 31;

    const int ag = blockIdx.x * 256 + w * 32;
    const bool active = (ag < NN);        // tiles always full (NN % 32 == 0)

    float lb = 0.0f, cp = 0.0f;
    int   pn = 0;

    const float* plab_b = p_labels + (size_t)b * NN * CC;

    if (active) {
        const float4* src4 = (const float4*)(plab_b + (size_t)ag * CC);
        float4* dst4 = (float4*)&sh[w][0];
        #pragma unroll
        for (int j = 0; j < 5; j++)
            dst4[l + 32 * j] = src4[l + 32 * j];
        if (l < 8)
            dst4[160 + l] = src4[160 + l];
    }
    __syncwarp();

    if (active) {
        const int n = ag + l;
        float4 a4 = ((const float4*)ancs)[n];
        float4 g4 = ((const float4*)g_bboxs)[(size_t)b * NN + n];
        float4 p4 = ((const float4*)p_bboxs)[(size_t)b * NN + n];
        float tx = 10.0f * (g4.x - a4.x) / a4.z;
        float ty = 10.0f * (g4.y - a4.y) / a4.w;
        float tw = 5.0f * __logf(g4.z / a4.z);
        float th = 5.0f * __logf(g4.w / a4.w);
        float sl1 = sl1f(p4.x - tx) + sl1f(p4.y - ty) +
                    sl1f(p4.z - tw) + sl1f(p4.w - th);

        const int lab = g_labels[(size_t)b * NN + n];

        const float* xr = &sh[w][l * CC];
        float m = xr[0];
        #pragma unroll
        for (int c = 1; c < CC; c++) m = fmaxf(m, xr[c]);
        float s = 0.0f;
        #pragma unroll
        for (int c = 0; c < CC; c++) s += __expf(xr[c] - m);
        float ce = m + __logf(s) - xr[lab];

        const bool pos = lab > 0;
        float neg = pos ? 0.0f : ce;      // ce >= 0 -> bit order = value order
        g_bits[(size_t)b * NN + n] = __float_as_uint(neg);
        if (pos) { pn = 1; lb = sl1; cp = ce; }
    }

    #pragma unroll
    for (int o = 16; o > 0; o >>= 1) {
        lb += __shfl_down_sync(0xFFFFFFFFu, lb, o);
        cp += __shfl_down_sync(0xFFFFFFFFu, cp, o);
        pn += __shfl_down_sync(0xFFFFFFFFu, pn, o);
    }
    if (l == 0) {
        int idx = ((b * SS) + blockIdx.x) * NW + w;
        g_part_lb[idx] = lb;
        g_part_cp[idx] = cp;
        g_part_pn[idx] = pn;
    }
}

// ---------------------------------------------------------------------------
// pick over 256-bin combined histogram: d* = max{d : suffix(d) >= kr},
// kr' = kr - suffix(d*+1). All 1024 threads must call (contains barriers).
// ---------------------------------------------------------------------------
__device__ __forceinline__ void pick256f(
    const unsigned int* cmb, unsigned int* chunkv,
    int* s_w, int* s_base, int* s_digit, int* s_kr,
    int kr, int lane, int wid)
{
    unsigned int p_val = 0, p_suf = 0;
    if (wid < 8) {
        p_val = cmb[wid * 32 + lane];
        p_suf = p_val;
        #pragma unroll
        for (int o = 1; o < 32; o <<= 1) {
            unsigned int t = __shfl_down_sync(0xFFFFFFFFu, p_suf, o);
            if (lane + o < 32) p_suf += t;
        }
        if (lane == 0) chunkv[wid] = p_suf;
    }
    __syncthreads();
    if (wid == 0) {
        unsigned int cs = (lane < 8) ? chunkv[lane] : 0u;
        #pragma unroll
        for (int o = 1; o < 32; o <<= 1) {
            unsigned int t = __shfl_down_sync(0xFFFFFFFFu, cs, o);
            if (lane + o < 32) cs += t;
        }
        unsigned int csn = __shfl_down_sync(0xFFFFFFFFu, cs, 1);
        if (lane == 31) csn = 0u;
        bool hit = (lane < 8) && ((int)cs >= kr) && ((int)csn < kr);
        unsigned int mm = __ballot_sync(0xFFFFFFFFu, hit);
        int src = __ffs(mm) - 1;
        unsigned int bse = __shfl_sync(0xFFFFFFFFu, csn, src);
        if (lane == 0) { *s_w = src; *s_base = (int)bse; }
    }
    __syncthreads();
    if (wid == *s_w) {
        unsigned int sufn = __shfl_down_sync(0xFFFFFFFFu, p_suf, 1);
        if (lane == 31) sufn = 0u;
        int above = *s_base + (int)sufn;
        if (above < kr && kr <= above + (int)p_val) {
            *s_digit = wid * 32 + lane;
            *s_kr = kr - above;
        }
    }
    __syncthreads();
}

// ---------------------------------------------------------------------------
// K2: radix top-k-sum, digits 8/8/8/8-exact. Scans 1-2: per-warp private u32
// histograms, match_any leader atomicAdd into OWN warp row (distinct addrs
// -> no serialization, no ordering hazard). Scan 3: sole fs/cg accumulation
// (fixes the R15 double count) + 256-bin spread hist + tiny compaction.
// ---------------------------------------------------------------------------
__global__ __launch_bounds__(1024) void k2_select()
{
    const int b    = blockIdx.x;
    const int tid  = threadIdx.x;
    const int lane = tid & 31;
    const int wid  = tid >> 5;

    __shared__ unsigned int h12[32 * 257];     // per-warp 256-bin hist (padded)
    __shared__ unsigned int combined[256];
    __shared__ unsigned int hist3[256];
    __shared__ unsigned int tiny[TINY_CAP];
    __shared__ unsigned int chunkv[32];
    __shared__ float warr[32];
    __shared__ float warr2[32];
    __shared__ int   wari[32];
    __shared__ int s_digit, s_kr, s_w, s_base;
    __shared__ float s_lb, s_cp;
    __shared__ int s_pn, s_nt;
    __shared__ unsigned int s_T;
    __shared__ float s_st;
    __shared__ int s_ct;

    // ---- reduce the 528 per-warp partials ----
    {
        float lbv = 0.0f, cpv = 0.0f; int pnv = 0;
        if (tid < NPART) {
            lbv = g_part_lb[b * NPART + tid];
            cpv = g_part_cp[b * NPART + tid];
            pnv = g_part_pn[b * NPART + tid];
        }
        #pragma unroll
        for (int o = 16; o > 0; o >>= 1) {
            lbv += __shfl_down_sync(0xFFFFFFFFu, lbv, o);
            cpv += __shfl_down_sync(0xFFFFFFFFu, cpv, o);
            pnv += __shfl_down_sync(0xFFFFFFFFu, pnv, o);
        }
        if (lane == 0) { warr[wid] = lbv; warr2[wid] = cpv; wari[wid] = pnv; }
        __syncthreads();
        if (wid == 0) {
            float a = warr[lane], c2 = warr2[lane]; int p = wari[lane];
            #pragma unroll
            for (int o = 16; o > 0; o >>= 1) {
                a  += __shfl_down_sync(0xFFFFFFFFu, a, o);
                c2 += __shfl_down_sync(0xFFFFFFFFu, c2, o);
                p  += __shfl_down_sync(0xFFFFFFFFu, p, o);
            }
            if (lane == 0) { s_lb = a; s_cp = c2; s_pn = p; }
        }
        __syncthreads();
    }
    const int   pn_t = s_pn;
    const float lb_t = s_lb;
    const float cp_t = s_cp;

    if (pn_t == 0) {
        if (tid == 0) {
            g_batch[b * 3 + 0] = 0.0f;
            g_batch[b * 3 + 1] = 0.0f;
            g_batch[b * 3 + 2] = 0.0f;
        }
        return;
    }

    const int k = min(3 * pn_t, NN);
    const uint4* vals4 = (const uint4*)(g_bits + (size_t)b * NN);  // 16B aligned

    float fs = 0.0f; int cg = 0;

    // ---- zero scratch ----
    for (int i = tid; i < 32 * 257; i += 1024) h12[i] = 0u;
    if (tid < 256) hist3[tid] = 0u;
    if (tid == 0) s_nt = 0;
    __syncthreads();

    // ---- SCAN 1: hist of top byte (v>>24), per-warp rows ----
    for (int base = 0; base < 5120; base += 1024) {
        int i = base + tid;
        bool valid = i < NV4;
        uint4 vv = valid ? vals4[i] : make_uint4(0u, 0u, 0u, 0u);
        #define S1V(v) do { unsigned int bin = (v) >> 24;                     \
            unsigned int key = valid ? bin : 0x1FFu;                          \
            unsigned int grp = __match_any_sync(0xFFFFFFFFu, key);            \
            if (valid && ((__ffs(grp) - 1) == lane))                          \
                atomicAdd(&h12[wid * 257 + bin], (unsigned int)__popc(grp)); } while (0)
        S1V(vv.x); S1V(vv.y); S1V(vv.z); S1V(vv.w);
        #undef S1V
    }
    __syncthreads();
    if (tid < 256) {
        unsigned int s = 0;
        #pragma unroll 8
        for (int w2 = 0; w2 < 32; w2++) s += h12[w2 * 257 + tid];
        combined[tid] = s;
    }
    __syncthreads();
    pick256f(combined, chunkv, &s_w, &s_base, &s_digit, &s_kr, k, lane, wid);
    const unsigned int d1 = (unsigned int)s_digit;
    const int kr1 = s_kr;
    __syncthreads();

    // ---- SCAN 2: hist of second byte, conditioned on top byte == d1 ----
    for (int i = tid; i < 32 * 257; i += 1024) h12[i] = 0u;
    __syncthreads();
    for (int base = 0; base < 5120; base += 1024) {
        int i = base + tid;
        bool valid = i < NV4;
        uint4 vv = valid ? vals4[i] : make_uint4(0u, 0u, 0u, 0u);
        #define S2V(v) do { unsigned int bv = (v);                            \
            bool sel = valid && ((bv >> 24) == d1);                           \
            unsigned int bin = (bv >> 16) & 0xFFu;                            \
            unsigned int key = sel ? bin : 0x1FFu;                            \
            unsigned int grp = __match_any_sync(0xFFFFFFFFu, key);            \
            if (sel && ((__ffs(grp) - 1) == lane))                            \
                atomicAdd(&h12[wid * 257 + bin], (unsigned int)__popc(grp)); } while (0)
        S2V(vv.x); S2V(vv.y); S2V(vv.z); S2V(vv.w);
        #undef S2V
    }
    __syncthreads();
    if (tid < 256) {
        unsigned int s = 0;
        #pragma unroll 8
        for (int w2 = 0; w2 < 32; w2++) s += h12[w2 * 257 + tid];
        combined[tid] = s;
    }
    __syncthreads();
    pick256f(combined, chunkv, &s_w, &s_base, &s_digit, &s_kr, kr1, lane, wid);
    const unsigned int d2 = (unsigned int)s_digit;
    const int kr2 = s_kr;
    __syncthreads();

    const unsigned int pref = (d1 << 8) | d2;     // 16-bit prefix

    // ---- SCAN 3: SOLE fs/cg accumulation (> 16-bit prefix) + hist3 + tiny ----
    for (int base = 0; base < 5120; base += 1024) {
        int i = base + tid;
        bool valid = i < NV4;
        uint4 vv = valid ? vals4[i] : make_uint4(0u, 0u, 0u, 0u);
        #define S3V(v) do { unsigned int bv = (v); unsigned int p16 = bv >> 16; \
            bool push = false;                                                \
            if (valid) {                                                      \
                if (p16 > pref) { fs += __uint_as_float(bv); cg++; }          \
                else if (p16 == pref) {                                       \
                    atomicAdd(&hist3[(bv >> 8) & 0xFFu], 1u);                 \
                    push = true;                                              \
                }                                                             \
            }                                                                 \
            unsigned int mk = __ballot_sync(0xFFFFFFFFu, push);               \
            if (mk) { int ldr = __ffs(mk) - 1; int bs = 0;                    \
                if (lane == ldr) bs = atomicAdd(&s_nt, __popc(mk));           \
                bs = __shfl_sync(0xFFFFFFFFu, bs, ldr);                       \
                if (push) { int pos = bs + __popc(mk & ((1u << lane) - 1u));  \
                    if (pos < TINY_CAP) tiny[pos] = bv; } } } while (0)
        S3V(vv.x); S3V(vv.y); S3V(vv.z); S3V(vv.w);
        #undef S3V
    }
    __syncthreads();
    pick256f(hist3, chunkv, &s_w, &s_base, &s_digit, &s_kr, kr2, lane, wid);
    const unsigned int d3 = (unsigned int)s_digit;
    const int kr3 = s_kr;
    const int nt = min(s_nt, TINY_CAP);
    __syncthreads();

    // tiny values with byte2 > d3 contribute fully
    for (int i = tid; i < nt; i += 1024) {
        unsigned int u = tiny[i];
        if (((u >> 8) & 0xFFu) > d3) { fs += __uint_as_float(u); cg++; }
    }

    // warp 0: exact kr3-th largest among tiny with byte2 == d3
    if (wid == 0) {
        unsigned int Tc = 0u;
        for (int i = lane; i < nt; i += 32) {
            unsigned int u = tiny[i];
            if (((u >> 8) & 0xFFu) != d3) continue;
            int g = 0, e = 0;
            for (int j = 0; j < nt; j++) {
                unsigned int w2 = tiny[j];
                if (((w2 >> 8) & 0xFFu) == d3) { g += (w2 > u); e += (w2 == u); }
            }
            if (g < kr3 && kr3 <= g + e) Tc = u;
        }
        #pragma unroll
        for (int o = 16; o > 0; o >>= 1) {
            unsigned int t = __shfl_down_sync(0xFFFFFFFFu, Tc, o);
            Tc = Tc > t ? Tc : t;
        }
        Tc = __shfl_sync(0xFFFFFFFFu, Tc, 0);
        float st = 0.0f; int ct = 0;
        for (int i = lane; i < nt; i += 32) {
            unsigned int u = tiny[i];
            if (((u >> 8) & 0xFFu) == d3 && u > Tc) { st += __uint_as_float(u); ct++; }
        }
        #pragma unroll
        for (int o = 16; o > 0; o >>= 1) {
            st += __shfl_down_sync(0xFFFFFFFFu, st, o);
            ct += __shfl_down_sync(0xFFFFFFFFu, ct, o);
        }
        if (lane == 0) { s_T = Tc; s_st = st; s_ct = ct; }
    }
    __syncthreads();

    // ---- final reduce fs/cg and combine ----
    #pragma unroll
    for (int o = 16; o > 0; o >>= 1) {
        fs += __shfl_down_sync(0xFFFFFFFFu, fs, o);
        cg += __shfl_down_sync(0xFFFFFFFFu, cg, o);
    }
    if (lane == 0) { warr[wid] = fs; wari[wid] = cg; }
    __syncthreads();
    if (wid == 0) {
        float x = warr[lane]; int c = wari[lane];
        #pragma unroll
        for (int o = 16; o > 0; o >>= 1) {
            x += __shfl_down_sync(0xFFFFFFFFu, x, o);
            c += __shfl_down_sync(0xFFFFFFFFu, c, o);
        }
        if (lane == 0) {
            float T = __uint_as_float(s_T);
            float sgt = x + s_st;
            int   cgt = c + s_ct;
            float topk = sgt + (float)(k - cgt) * T;
            float loss_labels = cp_t + topk;
            float posf = fmaxf((float)pn_t, FP32_EPS);
            float inv = 1.0f / posf;
            g_batch[b * 3 + 0] = (lb_t + loss_labels) * inv;
            g_batch[b * 3 + 1] = lb_t * inv;
            g_batch[b * 3 + 2] = loss_labels * inv;
        }
    }
}

// ---------------------------------------------------------------------------
// K3: mean over batches -> 3 scalars
// ---------------------------------------------------------------------------
__global__ void k3_final(float* __restrict__ out)
{
    __shared__ float r0[64], r1[64], r2[64];
    const int t = threadIdx.x;
    r0[t] = g_batch[t * 3 + 0];
    r1[t] = g_batch[t * 3 + 1];
    r2[t] = g_batch[t * 3 + 2];
    __syncthreads();
    for (int o = 32; o > 0; o >>= 1) {
        if (t < o) { r0[t] += r0[t + o]; r1[t] += r1[t + o]; r2[t] += r2[t + o]; }
        __syncthreads();
    }
    if (t == 0) {
        const float inv = 1.0f / (float)BB;
        out[0] = r0[0] * inv;
        out[1] = r1[0] * inv;
        out[2] = r2[0] * inv;
    }
}

extern "C" void kernel_launch(void* const* d_in, const int* in_sizes, int n_in,
                              void* d_out, int out_size)
{
    const float* p_bboxs  = (const float*)d_in[0];
    const float* g_bboxs  = (const float*)d_in[1];
    const float* p_labels = (const float*)d_in[2];
    const int*   g_labels = (const int*)d_in[3];
    const float* ancs     = (const float*)d_in[4];
    float* out = (float*)d_out;

    dim3 g1(SS, BB);
    k1_main<<<g1, 256>>>(p_bboxs, g_bboxs, p_labels, g_labels, ancs);
    k2_select<<<BB, 1024>>>();
    k3_final<<<1, 64>>>(out);
}